// round 9
// baseline (speedup 1.0000x reference)
#include <cuda_runtime.h>
#include <cstdint>
#include <cstddef>

// Problem dims (fixed by the reference)
#define B_SZ 32
#define T_SZ 2048
#define F_SZ 512
#define H_SZ 512
#define G4H  2048   // 4*H

// ---------------- packed fp32x2 helpers (sm_103a FFMA2) ----------------
__device__ __forceinline__ unsigned long long pack2(float lo, float hi) {
    unsigned long long r;
    asm("mov.b64 %0, {%1, %2};" : "=l"(r) : "f"(lo), "f"(hi));
    return r;
}
__device__ __forceinline__ void ffma2(unsigned long long& d,
                                      unsigned long long a, unsigned long long b) {
    asm("fma.rn.f32x2 %0, %1, %2, %3;" : "=l"(d) : "l"(a), "l"(b), "l"(d));
}
__device__ __forceinline__ unsigned long long add2(unsigned long long a,
                                                   unsigned long long b) {
    unsigned long long r;
    asm("add.rn.f32x2 %0, %1, %2;" : "=l"(r) : "l"(a), "l"(b));
    return r;
}
__device__ __forceinline__ float sum2(unsigned long long p) {
    float lo, hi;
    asm("mov.b64 {%0, %1}, %2;" : "=f"(lo), "=f"(hi) : "l"(p));
    return lo + hi;
}

// ---------------- scratch ----------------
__device__ float g_xw[(size_t)T_SZ * B_SZ * G4H];  // x@Wi + b, [t][b][4H]
__device__ float g_h[2 * B_SZ * H_SZ];             // double-buffered hidden state
// Per-CTA arrival slots: group g uses g_slot[g*32 .. g*32+31] (one 128B line/group).
__device__ unsigned g_slot[4 * 32];

// ---------------- sync primitives (no atomics, no MEMBAR.GPU) ----------------
__device__ __forceinline__ void slot_release(unsigned* p, unsigned v) {
    asm volatile("st.release.gpu.global.u32 [%0], %1;" :: "l"(p), "r"(v) : "memory");
}
__device__ __forceinline__ unsigned slot_acquire(const unsigned* p) {
    unsigned v;
    asm volatile("ld.acquire.gpu.global.u32 %0, [%1];" : "=r"(v) : "l"(p) : "memory");
    return v;
}

// ---------------- Pre-GEMM with FFMA2 + duplicated-A smem ----------------
// g_xw[t*B+b][n] = sum_k x[b][t][k]*Wi[k][n] + bias[n]
// M = B*T = 65536 (row m = b*T+t), N = 2048, K = 512.
// 128x128 tile, BK=8, 256 threads; 8(m) x 4(n-pair) packed register tile.
__global__ void __launch_bounds__(256) pregemm_kernel(
    const float* __restrict__ x, const float* __restrict__ Wi,
    const float* __restrict__ bias)
{
    __shared__ float As2[8][256];   // duplicated: As2[kk][2m] = As2[kk][2m+1]
    __shared__ float Bs[8][128];

    const int tid = threadIdx.x;
    // One block resets the barrier slots for the recurrence kernel (stream
    // order guarantees pregemm completes before lstm_rec starts).
    if (blockIdx.x == 0 && blockIdx.y == 0 && tid < 128) g_slot[tid] = 0u;

    const int m0 = blockIdx.y * 128;
    const int n0 = blockIdx.x * 128;
    const int tx = tid & 15;        // n micro (8 floats = 4 pairs)
    const int ty = tid >> 4;        // m micro

    const int ar  = tid >> 1;
    const int ac4 = (tid & 1) * 4;
    const int br  = tid >> 5;
    const int bc4 = (tid & 31) * 4;

    unsigned long long acc2[8][4];
#pragma unroll
    for (int i = 0; i < 8; i++)
#pragma unroll
        for (int j = 0; j < 4; j++) acc2[i][j] = 0ull;

    for (int k0 = 0; k0 < F_SZ; k0 += 8) {
        float4 av = *(const float4*)(x + (size_t)(m0 + ar) * F_SZ + k0 + ac4);
        *(float2*)&As2[ac4 + 0][2 * ar] = make_float2(av.x, av.x);
        *(float2*)&As2[ac4 + 1][2 * ar] = make_float2(av.y, av.y);
        *(float2*)&As2[ac4 + 2][2 * ar] = make_float2(av.z, av.z);
        *(float2*)&As2[ac4 + 3][2 * ar] = make_float2(av.w, av.w);
        *(float4*)&Bs[br][bc4] = *(const float4*)(Wi + (size_t)(k0 + br) * G4H + n0 + bc4);
        __syncthreads();

#pragma unroll
        for (int kk = 0; kk < 8; kk++) {
            const ulonglong2* ap = (const ulonglong2*)&As2[kk][ty * 16];
            const ulonglong2* bp = (const ulonglong2*)&Bs[kk][tx * 8];
            ulonglong2 b01 = bp[0];
            ulonglong2 b23 = bp[1];
#pragma unroll
            for (int p = 0; p < 4; p++) {
                ulonglong2 aa = ap[p];          // (a_{2p},a_{2p}), (a_{2p+1},a_{2p+1})
                ffma2(acc2[2 * p][0], aa.x, b01.x);
                ffma2(acc2[2 * p][1], aa.x, b01.y);
                ffma2(acc2[2 * p][2], aa.x, b23.x);
                ffma2(acc2[2 * p][3], aa.x, b23.y);
                ffma2(acc2[2 * p + 1][0], aa.y, b01.x);
                ffma2(acc2[2 * p + 1][1], aa.y, b01.y);
                ffma2(acc2[2 * p + 1][2], aa.y, b23.x);
                ffma2(acc2[2 * p + 1][3], aa.y, b23.y);
            }
        }
        __syncthreads();
    }

    // epilogue: remap row m=(b*T+t) -> xw row (t*B+b), add bias
    const float* bp = bias + n0 + tx * 8;
    float bb[8];
    *(float4*)(bb)     = *(const float4*)(bp);
    *(float4*)(bb + 4) = *(const float4*)(bp + 4);
#pragma unroll
    for (int i = 0; i < 8; i++) {
        const int m    = m0 + ty * 8 + i;
        const int bidx = m >> 11;       // / T
        const int tdx  = m & (T_SZ - 1);
        float* op = g_xw + ((size_t)tdx * B_SZ + bidx) * G4H + n0 + tx * 8;
        float o[8];
        union { unsigned long long u; float2 f; } cv;
#pragma unroll
        for (int j = 0; j < 4; j++) {
            cv.u = acc2[i][j];
            o[2 * j]     = cv.f.x + bb[2 * j];
            o[2 * j + 1] = cv.f.y + bb[2 * j + 1];
        }
        *(float4*)(op)     = *(const float4*)(o);
        *(float4*)(op + 4) = *(const float4*)(o + 4);
    }
}

// ---------------- Recurrence: persistent, 4 groups x 32 CTAs ----------------
// Group g: batches [8g, 8g+8). CTA r in group owns 64 z-columns
// (gate q, h-col r*16+jj). Wh slice lives in REGISTERS (64 f32x2/thread).
// Thread (tid): col lc = tid>>2 (0..63), k-chunk kc = tid&3 (128 k each).

#define HS_CHUNK 132                       // 128 + 4 pad (bank spread)
#define HS_BB    (4 * HS_CHUNK)            // 528 floats per batch row

__global__ void __launch_bounds__(256) lstm_rec_kernel(
    const float* __restrict__ c0, const float* __restrict__ h0,
    const float* __restrict__ Wh,
    float* __restrict__ outC, float* __restrict__ outH, float* __restrict__ outY)
{
    __shared__ float h_s[8 * HS_BB];   // staged h, padded per k-chunk
    __shared__ float z_s[8 * 64];      // hw partials
    __shared__ float c_s[128];         // cell state (8 batches x 16 cols)

    const int tid = threadIdx.x;
    const int grp = blockIdx.x >> 5;
    const int r   = blockIdx.x & 31;
    const int b0  = grp * 8;
    unsigned* const my_slot   = &g_slot[grp * 32 + r];
    const unsigned* grp_slots = &g_slot[grp * 32];

    const int lc  = tid >> 2;                         // 0..63 local column
    const int kc  = tid & 3;                          // k chunk
    const int gcol = ((lc >> 4) << 9) + (r << 4) + (lc & 15);

    // ---- Load this thread's Wh slice into registers (packed k-pairs) ----
    unsigned long long w2[64];
#pragma unroll
    for (int j = 0; j < 64; j++) {
        float lo = Wh[(size_t)(kc * 128 + 2 * j)     * G4H + gcol];
        float hi = Wh[(size_t)(kc * 128 + 2 * j + 1) * G4H + gcol];
        w2[j] = pack2(lo, hi);
    }

    // Init c (block-local) and h buffer 0 (owned slice only)
    if (tid < 128) {
        int bb = tid >> 4, jj = tid & 15;
        int b = b0 + bb, j = (r << 4) + jj;
        c_s[tid] = c0[b * H_SZ + j];
        g_h[b * H_SZ + j] = h0[b * H_SZ + j];
    }
    __syncthreads();
    if (tid == 0) slot_release(my_slot, 1u);   // h buffer 0 published

    for (int t = 0; t < T_SZ; t++) {
        const int buf = t & 1;
        const unsigned target = (unsigned)(t + 1);

        // ---- wait: all group CTAs have published h[buf] ----
        if (tid < 32) {
            unsigned v;
            do { v = slot_acquire(grp_slots + tid); }
            while (!__all_sync(0xFFFFFFFFu, v >= target));
        }
        __syncthreads();

        // Stage h for this group's 8 batches into padded smem.
        const float* hg = g_h + buf * (B_SZ * H_SZ) + b0 * H_SZ;
#pragma unroll
        for (int it = 0; it < 4; it++) {
            int idx = tid + it * 256;              // 0..1023 float4 slots
            int bb = idx >> 7, q = idx & 127;      // q: float4 index in [0,128)
            float4 v = __ldcg((const float4*)(hg + bb * H_SZ) + q);
            *(float4*)(h_s + bb * HS_BB + (q >> 5) * HS_CHUNK + (q & 31) * 4) = v;
        }

        // Prefetch xw for the activation phase (depends only on t).
        float xw0 = 0.f, xw1 = 0.f, xw2 = 0.f, xw3 = 0.f;
        if (tid < 128) {
            int bb = tid >> 4, jj = tid & 15;
            const float* xp = g_xw + ((size_t)t * B_SZ + b0 + bb) * G4H + (r << 4) + jj;
            xw0 = __ldg(xp);
            xw1 = __ldg(xp + 512);
            xw2 = __ldg(xp + 1024);
            xw3 = __ldg(xp + 1536);
        }
        __syncthreads();

        // ---- h @ Wh partials: per batch, 64 FFMA2 against register Wh ----
#pragma unroll 2
        for (int bbt = 0; bbt < 8; bbt++) {
            const ulonglong2* hp =
                (const ulonglong2*)(h_s + bbt * HS_BB + kc * HS_CHUNK);
            unsigned long long a0 = 0ull, a1 = 0ull, a2 = 0ull, a3 = 0ull;
#pragma unroll
            for (int i = 0; i < 32; i += 2) {
                ulonglong2 hA = hp[i];
                ulonglong2 hB = hp[i + 1];
                ffma2(a0, w2[2 * i],     hA.x);
                ffma2(a1, w2[2 * i + 1], hA.y);
                ffma2(a2, w2[2 * i + 2], hB.x);
                ffma2(a3, w2[2 * i + 3], hB.y);
            }
            float s = sum2(add2(add2(a0, a1), add2(a2, a3)));
            // reduce the 4 k-chunks (lanes 4c..4c+3 of the same warp)
            s += __shfl_xor_sync(0xFFFFFFFFu, s, 1);
            s += __shfl_xor_sync(0xFFFFFFFFu, s, 2);
            if (kc == 0) z_s[bbt * 64 + lc] = s;
        }
        __syncthreads();

        // ---- gates + state update (128 threads: 8 batches x 16 h-cols) ----
        if (tid < 128) {
            int bb = tid >> 4, jj = tid & 15;
            float zi = z_s[bb * 64 + jj]      + xw0;
            float zf = z_s[bb * 64 + 16 + jj] + xw1;
            float zg = z_s[bb * 64 + 32 + jj] + xw2;
            float zo = z_s[bb * 64 + 48 + jj] + xw3;
            float ig = 1.f / (1.f + __expf(-zi));
            float fg = 1.f / (1.f + __expf(-zf));
            float gg = tanhf(zg);
            float og = 1.f / (1.f + __expf(-zo));
            float c  = c_s[tid];
            float cn = fmaf(fg, c, ig * gg);
            c_s[tid] = cn;
            float hn = og * tanhf(cn);
            int b = b0 + bb, j = (r << 4) + jj;
            g_h[(buf ^ 1) * (B_SZ * H_SZ) + b * H_SZ + j] = hn;
            outY[((size_t)b * T_SZ + t) * H_SZ + j] = hn;
            if (t == T_SZ - 1) {
                if (outC) outC[b * H_SZ + j] = cn;
                if (outH) outH[b * H_SZ + j] = hn;
            }
        }
        __syncthreads();
        if (tid == 0) slot_release(my_slot, target + 1u);  // h[buf^1] published
    }
}

// ---------------- launch ----------------
extern "C" void kernel_launch(void* const* d_in, const int* in_sizes, int n_in,
                              void* d_out, int out_size)
{
    const float* x    = (const float*)d_in[0];
    const float* c0   = (const float*)d_in[1];
    const float* h0   = (const float*)d_in[2];
    const float* Wi   = (const float*)d_in[3];
    const float* Wh   = (const float*)d_in[4];
    const float* bias = (const float*)d_in[5];

    float* out  = (float*)d_out;
    float* outC = nullptr;
    float* outH = nullptr;
    float* outY = out;
    const long long full = 2LL * B_SZ * H_SZ + (long long)B_SZ * T_SZ * H_SZ;
    if ((long long)out_size == full) {
        outC = out;
        outH = out + B_SZ * H_SZ;
        outY = out + 2 * B_SZ * H_SZ;
    }

    pregemm_kernel<<<dim3(G4H / 128, (B_SZ * T_SZ) / 128), 256>>>(x, Wi, bias);
    lstm_rec_kernel<<<128, 256>>>(c0, h0, Wh, outC, outH, outY);
}

// round 12
// speedup vs baseline: 1.0584x; 1.0584x over previous
#include <cuda_runtime.h>
#include <cstdint>
#include <cstddef>

// Problem dims (fixed by the reference)
#define B_SZ 32
#define T_SZ 2048
#define F_SZ 512
#define H_SZ 512
#define G4H  2048   // 4*H

// ---------------- packed fp32x2 helpers (sm_103a FFMA2) ----------------
__device__ __forceinline__ unsigned long long pack2(float lo, float hi) {
    unsigned long long r;
    asm("mov.b64 %0, {%1, %2};" : "=l"(r) : "f"(lo), "f"(hi));
    return r;
}
__device__ __forceinline__ void ffma2(unsigned long long& d,
                                      unsigned long long a, unsigned long long b) {
    asm("fma.rn.f32x2 %0, %1, %2, %3;" : "=l"(d) : "l"(a), "l"(b), "l"(d));
}
__device__ __forceinline__ unsigned long long add2(unsigned long long a,
                                                   unsigned long long b) {
    unsigned long long r;
    asm("add.rn.f32x2 %0, %1, %2;" : "=l"(r) : "l"(a), "l"(b));
    return r;
}
__device__ __forceinline__ float sum2(unsigned long long p) {
    float lo, hi;
    asm("mov.b64 {%0, %1}, %2;" : "=f"(lo), "=f"(hi) : "l"(p));
    return lo + hi;
}

// ---------------- scratch ----------------
__device__ float g_xw[(size_t)T_SZ * B_SZ * G4H];  // x@Wi + b, [t][b][4H]
__device__ float g_h[2 * B_SZ * H_SZ];             // double-buffered hidden state
// Flags: [sub(2)][grp(4)][consumer(32)][producer(32)] u32.
// Each (sub,grp,consumer) owns a PRIVATE 128B line -> no hot LTS slice.
#define FLAG_WORDS (2 * 4 * 32 * 32)
__device__ unsigned g_flag[FLAG_WORDS];

// ---------------- sync primitives ----------------
__device__ __forceinline__ void slot_release(unsigned* p, unsigned v) {
    asm volatile("st.release.gpu.global.u32 [%0], %1;" :: "l"(p), "r"(v) : "memory");
}
__device__ __forceinline__ unsigned slot_acquire(const unsigned* p) {
    unsigned v;
    asm volatile("ld.acquire.gpu.global.u32 %0, [%1];" : "=r"(v) : "l"(p) : "memory");
    return v;
}

// ---------------- Pre-GEMM with FFMA2 + duplicated-A smem ----------------
// g_xw[t*B+b][n] = sum_k x[b][t][k]*Wi[k][n] + bias[n]
// M = B*T = 65536 (row m = b*T+t), N = 2048, K = 512.
__global__ void __launch_bounds__(256) pregemm_kernel(
    const float* __restrict__ x, const float* __restrict__ Wi,
    const float* __restrict__ bias)
{
    __shared__ float As2[8][256];   // duplicated: As2[kk][2m] = As2[kk][2m+1]
    __shared__ float Bs[8][128];

    const int tid = threadIdx.x;
    // Block (0,0) resets the flag array for the recurrence kernel (stream
    // order guarantees pregemm completes before lstm_rec starts).
    if (blockIdx.x == 0 && blockIdx.y == 0) {
        for (int i = tid; i < FLAG_WORDS; i += 256) g_flag[i] = 0u;
    }

    const int m0 = blockIdx.y * 128;
    const int n0 = blockIdx.x * 128;
    const int tx = tid & 15;        // n micro (8 floats = 4 pairs)
    const int ty = tid >> 4;        // m micro

    const int ar  = tid >> 1;
    const int ac4 = (tid & 1) * 4;
    const int br  = tid >> 5;
    const int bc4 = (tid & 31) * 4;

    unsigned long long acc2[8][4];
#pragma unroll
    for (int i = 0; i < 8; i++)
#pragma unroll
        for (int j = 0; j < 4; j++) acc2[i][j] = 0ull;

    for (int k0 = 0; k0 < F_SZ; k0 += 8) {
        float4 av = *(const float4*)(x + (size_t)(m0 + ar) * F_SZ + k0 + ac4);
        *(float2*)&As2[ac4 + 0][2 * ar] = make_float2(av.x, av.x);
        *(float2*)&As2[ac4 + 1][2 * ar] = make_float2(av.y, av.y);
        *(float2*)&As2[ac4 + 2][2 * ar] = make_float2(av.z, av.z);
        *(float2*)&As2[ac4 + 3][2 * ar] = make_float2(av.w, av.w);
        *(float4*)&Bs[br][bc4] = *(const float4*)(Wi + (size_t)(k0 + br) * G4H + n0 + bc4);
        __syncthreads();

#pragma unroll
        for (int kk = 0; kk < 8; kk++) {
            const ulonglong2* ap = (const ulonglong2*)&As2[kk][ty * 16];
            const ulonglong2* bp = (const ulonglong2*)&Bs[kk][tx * 8];
            ulonglong2 b01 = bp[0];
            ulonglong2 b23 = bp[1];
#pragma unroll
            for (int p = 0; p < 4; p++) {
                ulonglong2 aa = ap[p];
                ffma2(acc2[2 * p][0], aa.x, b01.x);
                ffma2(acc2[2 * p][1], aa.x, b01.y);
                ffma2(acc2[2 * p][2], aa.x, b23.x);
                ffma2(acc2[2 * p][3], aa.x, b23.y);
                ffma2(acc2[2 * p + 1][0], aa.y, b01.x);
                ffma2(acc2[2 * p + 1][1], aa.y, b01.y);
                ffma2(acc2[2 * p + 1][2], aa.y, b23.x);
                ffma2(acc2[2 * p + 1][3], aa.y, b23.y);
            }
        }
        __syncthreads();
    }

    const float* bp = bias + n0 + tx * 8;
    float bb[8];
    *(float4*)(bb)     = *(const float4*)(bp);
    *(float4*)(bb + 4) = *(const float4*)(bp + 4);
#pragma unroll
    for (int i = 0; i < 8; i++) {
        const int m    = m0 + ty * 8 + i;
        const int bidx = m >> 11;       // / T
        const int tdx  = m & (T_SZ - 1);
        float* op = g_xw + ((size_t)tdx * B_SZ + bidx) * G4H + n0 + tx * 8;
        float o[8];
        union { unsigned long long u; float2 f; } cv;
#pragma unroll
        for (int j = 0; j < 4; j++) {
            cv.u = acc2[i][j];
            o[2 * j]     = cv.f.x + bb[2 * j];
            o[2 * j + 1] = cv.f.y + bb[2 * j + 1];
        }
        *(float4*)(op)     = *(const float4*)(o);
        *(float4*)(op + 4) = *(const float4*)(o + 4);
    }
}

// ---------------- Recurrence: persistent, 4 groups x 32 CTAs ----------------
// Group g: batches [8g, 8g+8), processed as two interleaved subgroups
// A = [8g, 8g+4), B = [8g+4, 8g+8). CTA r owns 64 z-columns; Wh slice in
// registers (shared across all batches). Publishing A before computing B
// hides the inter-CTA handoff latency behind compute.

#define HS_CHUNK 132                       // 128 + 4 pad (bank spread)
#define HS_BB    (4 * HS_CHUNK)            // 528 floats per batch row

__global__ void __launch_bounds__(256) lstm_rec_kernel(
    const float* __restrict__ c0, const float* __restrict__ h0,
    const float* __restrict__ Wh,
    float* __restrict__ outC, float* __restrict__ outH, float* __restrict__ outY)
{
    __shared__ float h_s[4 * HS_BB];   // staged h for one subgroup (4 batches)
    __shared__ float z_s[256];         // hw partials (4 batches x 64 cols)
    __shared__ float c_s[128];         // cell state (8 batches x 16 cols)

    const int tid = threadIdx.x;
    const int grp = blockIdx.x >> 5;
    const int r   = blockIdx.x & 31;
    const int b0  = grp * 8;

    const int lc  = tid >> 2;                         // 0..63 local column
    const int kc  = tid & 3;                          // k chunk
    const int gcol = ((lc >> 4) << 9) + (r << 4) + (lc & 15);

    // ---- Load this thread's Wh slice into registers (packed k-pairs) ----
    unsigned long long w2[64];
#pragma unroll
    for (int j = 0; j < 64; j++) {
        float lo = Wh[(size_t)(kc * 128 + 2 * j)     * G4H + gcol];
        float hi = Wh[(size_t)(kc * 128 + 2 * j + 1) * G4H + gcol];
        w2[j] = pack2(lo, hi);
    }

    // Init c (block-local) and h buffer 0 (owned slice only)
    if (tid < 128) {
        int bb = tid >> 4, jj = tid & 15;
        int b = b0 + bb, j = (r << 4) + jj;
        c_s[tid] = c0[b * H_SZ + j];
        g_h[b * H_SZ + j] = h0[b * H_SZ + j];
    }
    __syncthreads();
    if (tid < 32) {   // publish h(0) for both subgroups: value 1
        slot_release(&g_flag[(((0 * 4 + grp) * 32) + tid) * 32 + r], 1u);
        slot_release(&g_flag[(((1 * 4 + grp) * 32) + tid) * 32 + r], 1u);
    }

    for (int t = 0; t < T_SZ; t++) {
        const int buf = t & 1;
        const unsigned target = (unsigned)(t + 1);

        // Prefetch xw for both subgroups (depends only on t) - off critical path.
        float xwv[2][4];
        if (tid < 64) {
            int bb = tid >> 4, jj = tid & 15;
            const float* base = g_xw + ((size_t)t * B_SZ + b0) * G4H + (r << 4) + jj;
#pragma unroll
            for (int ph = 0; ph < 2; ph++)
#pragma unroll
                for (int q = 0; q < 4; q++)
                    xwv[ph][q] = __ldg(base + (size_t)(bb + 4 * ph) * G4H + q * H_SZ);
        }

#pragma unroll 1
        for (int ph = 0; ph < 2; ph++) {
            // ---- wait: all producers published h[buf] for this subgroup ----
            if (tid < 32) {
                const unsigned* fl = &g_flag[(((ph * 4 + grp) * 32) + r) * 32];
                unsigned v;
                do { v = slot_acquire(fl + tid); }
                while (!__all_sync(0xFFFFFFFFu, v >= target));
            }
            __syncthreads();   // ALL warps must observe the publish before loading h

            // ---- stage h for this subgroup's 4 batches ----
            const float* hg = g_h + buf * (B_SZ * H_SZ) + (b0 + ph * 4) * H_SZ;
#pragma unroll
            for (int it = 0; it < 2; it++) {
                int idx = tid + it * 256;          // 0..511 float4 slots
                int bbl = idx >> 7, q = idx & 127;
                float4 v = __ldcg((const float4*)(hg + bbl * H_SZ) + q);
                *(float4*)(h_s + bbl * HS_BB + (q >> 5) * HS_CHUNK + (q & 31) * 4) = v;
            }
            __syncthreads();

            // ---- h @ Wh partials: 4 batches against register Wh ----
#pragma unroll 2
            for (int bbt = 0; bbt < 4; bbt++) {
                const ulonglong2* hp =
                    (const ulonglong2*)(h_s + bbt * HS_BB + kc * HS_CHUNK);
                unsigned long long a0 = 0ull, a1 = 0ull, a2 = 0ull, a3 = 0ull;
#pragma unroll
                for (int i = 0; i < 32; i += 2) {
                    ulonglong2 hA = hp[i];
                    ulonglong2 hB = hp[i + 1];
                    ffma2(a0, w2[2 * i],     hA.x);
                    ffma2(a1, w2[2 * i + 1], hA.y);
                    ffma2(a2, w2[2 * i + 2], hB.x);
                    ffma2(a3, w2[2 * i + 3], hB.y);
                }
                float s = sum2(add2(add2(a0, a1), add2(a2, a3)));
                s += __shfl_xor_sync(0xFFFFFFFFu, s, 1);
                s += __shfl_xor_sync(0xFFFFFFFFu, s, 2);
                if (kc == 0) z_s[bbt * 64 + lc] = s;
            }
            __syncthreads();

            // ---- gates + state update (64 threads: 4 batches x 16 cols) ----
            if (tid < 64) {
                int bb = tid >> 4, jj = tid & 15;
                float zi = z_s[bb * 64 + jj]      + xwv[ph][0];
                float zf = z_s[bb * 64 + 16 + jj] + xwv[ph][1];
                float zg = z_s[bb * 64 + 32 + jj] + xwv[ph][2];
                float zo = z_s[bb * 64 + 48 + jj] + xwv[ph][3];
                float ig = 1.f / (1.f + __expf(-zi));
                float fg = 1.f / (1.f + __expf(-zf));
                float gg = tanhf(zg);
                float og = 1.f / (1.f + __expf(-zo));
                float c  = c_s[tid + ph * 64];
                float cn = fmaf(fg, c, ig * gg);
                c_s[tid + ph * 64] = cn;
                float hn = og * tanhf(cn);
                int b = b0 + bb + 4 * ph, j = (r << 4) + jj;
                g_h[(buf ^ 1) * (B_SZ * H_SZ) + b * H_SZ + j] = hn;
                outY[((size_t)b * T_SZ + t) * H_SZ + j] = hn;
                if (t == T_SZ - 1) {
                    if (outC) outC[b * H_SZ + j] = cn;
                    if (outH) outH[b * H_SZ + j] = hn;
                }
            }
            __syncthreads();   // order all gate-threads' stores before flags

            // ---- publish h[buf^1] for this subgroup (scattered lines) ----
            if (tid < 32)
                slot_release(&g_flag[(((ph * 4 + grp) * 32) + tid) * 32 + r],
                             target + 1u);
        }
    }
}

// ---------------- launch ----------------
extern "C" void kernel_launch(void* const* d_in, const int* in_sizes, int n_in,
                              void* d_out, int out_size)
{
    const float* x    = (const float*)d_in[0];
    const float* c0   = (const float*)d_in[1];
    const float* h0   = (const float*)d_in[2];
    const float* Wi   = (const float*)d_in[3];
    const float* Wh   = (const float*)d_in[4];
    const float* bias = (const float*)d_in[5];

    float* out  = (float*)d_out;
    float* outC = nullptr;
    float* outH = nullptr;
    float* outY = out;
    const long long full = 2LL * B_SZ * H_SZ + (long long)B_SZ * T_SZ * H_SZ;
    if ((long long)out_size == full) {
        outC = out;
        outH = out + B_SZ * H_SZ;
        outY = out + 2 * B_SZ * H_SZ;
    }

    pregemm_kernel<<<dim3(G4H / 128, (B_SZ * T_SZ) / 128), 256>>>(x, Wi, bias);
    lstm_rec_kernel<<<128, 256>>>(c0, h0, Wh, outC, outH, outY);
}

// round 13
// speedup vs baseline: 1.5178x; 1.4341x over previous
#include <cuda_runtime.h>
#include <cstdint>
#include <cstddef>

// Problem dims (fixed by the reference)
#define B_SZ 32
#define T_SZ 2048
#define F_SZ 512
#define H_SZ 512
#define G4H  2048   // 4*H

// ---------------- packed fp32x2 helpers (sm_103a FFMA2) ----------------
__device__ __forceinline__ unsigned long long pack2(float lo, float hi) {
    unsigned long long r;
    asm("mov.b64 %0, {%1, %2};" : "=l"(r) : "f"(lo), "f"(hi));
    return r;
}
__device__ __forceinline__ void ffma2(unsigned long long& d,
                                      unsigned long long a, unsigned long long b) {
    asm("fma.rn.f32x2 %0, %1, %2, %3;" : "=l"(d) : "l"(a), "l"(b), "l"(d));
}
__device__ __forceinline__ unsigned long long add2(unsigned long long a,
                                                   unsigned long long b) {
    unsigned long long r;
    asm("add.rn.f32x2 %0, %1, %2;" : "=l"(r) : "l"(a), "l"(b));
    return r;
}
__device__ __forceinline__ float sum2(unsigned long long p) {
    float lo, hi;
    asm("mov.b64 {%0, %1}, %2;" : "=f"(lo), "=f"(hi) : "l"(p));
    return lo + hi;
}

// ---------------- fast activations (MUFU-based, on the serial chain) ----------
__device__ __forceinline__ float fsig(float x) {
    return __fdividef(1.f, 1.f + __expf(-x));
}
__device__ __forceinline__ float ftanh(float x) {
    return 1.f - __fdividef(2.f, __expf(2.f * x) + 1.f);
}

// ---------------- scratch ----------------
__device__ float g_xw[(size_t)T_SZ * B_SZ * G4H];  // x@Wi + b, [t][b][4H]
__device__ float g_h[2 * B_SZ * H_SZ];             // double-buffered hidden state
// Flags: [grp(4)][consumer(32)][producer(32)] u32.
// Each (grp,consumer) owns a PRIVATE 128B line -> consumer polls ONE line.
#define FLAG_WORDS (4 * 32 * 32)
__device__ __align__(128) unsigned g_flag[FLAG_WORDS];

// ---------------- sync primitives ----------------
__device__ __forceinline__ void slot_release(unsigned* p, unsigned v) {
    asm volatile("st.release.gpu.global.u32 [%0], %1;" :: "l"(p), "r"(v) : "memory");
}
__device__ __forceinline__ unsigned slot_acquire(const unsigned* p) {
    unsigned v;
    asm volatile("ld.acquire.gpu.global.u32 %0, [%1];" : "=r"(v) : "l"(p) : "memory");
    return v;
}

// ---------------- Pre-GEMM with FFMA2 + duplicated-A smem ----------------
// g_xw[t*B+b][n] = sum_k x[b][t][k]*Wi[k][n] + bias[n]
// M = B*T = 65536 (row m = b*T+t), N = 2048, K = 512.
__global__ void __launch_bounds__(256) pregemm_kernel(
    const float* __restrict__ x, const float* __restrict__ Wi,
    const float* __restrict__ bias)
{
    __shared__ float As2[8][256];   // duplicated: As2[kk][2m] = As2[kk][2m+1]
    __shared__ float Bs[8][128];

    const int tid = threadIdx.x;
    // Block (0,0) resets the flag array for the recurrence kernel (stream
    // order guarantees pregemm completes before lstm_rec starts).
    if (blockIdx.x == 0 && blockIdx.y == 0) {
        for (int i = tid; i < FLAG_WORDS; i += 256) g_flag[i] = 0u;
    }

    const int m0 = blockIdx.y * 128;
    const int n0 = blockIdx.x * 128;
    const int tx = tid & 15;        // n micro (8 floats = 4 pairs)
    const int ty = tid >> 4;        // m micro

    const int ar  = tid >> 1;
    const int ac4 = (tid & 1) * 4;
    const int br  = tid >> 5;
    const int bc4 = (tid & 31) * 4;

    unsigned long long acc2[8][4];
#pragma unroll
    for (int i = 0; i < 8; i++)
#pragma unroll
        for (int j = 0; j < 4; j++) acc2[i][j] = 0ull;

    for (int k0 = 0; k0 < F_SZ; k0 += 8) {
        float4 av = *(const float4*)(x + (size_t)(m0 + ar) * F_SZ + k0 + ac4);
        *(float2*)&As2[ac4 + 0][2 * ar] = make_float2(av.x, av.x);
        *(float2*)&As2[ac4 + 1][2 * ar] = make_float2(av.y, av.y);
        *(float2*)&As2[ac4 + 2][2 * ar] = make_float2(av.z, av.z);
        *(float2*)&As2[ac4 + 3][2 * ar] = make_float2(av.w, av.w);
        *(float4*)&Bs[br][bc4] = *(const float4*)(Wi + (size_t)(k0 + br) * G4H + n0 + bc4);
        __syncthreads();

#pragma unroll
        for (int kk = 0; kk < 8; kk++) {
            const ulonglong2* ap = (const ulonglong2*)&As2[kk][ty * 16];
            const ulonglong2* bp = (const ulonglong2*)&Bs[kk][tx * 8];
            ulonglong2 b01 = bp[0];
            ulonglong2 b23 = bp[1];
#pragma unroll
            for (int p = 0; p < 4; p++) {
                ulonglong2 aa = ap[p];
                ffma2(acc2[2 * p][0], aa.x, b01.x);
                ffma2(acc2[2 * p][1], aa.x, b01.y);
                ffma2(acc2[2 * p][2], aa.x, b23.x);
                ffma2(acc2[2 * p][3], aa.x, b23.y);
                ffma2(acc2[2 * p + 1][0], aa.y, b01.x);
                ffma2(acc2[2 * p + 1][1], aa.y, b01.y);
                ffma2(acc2[2 * p + 1][2], aa.y, b23.x);
                ffma2(acc2[2 * p + 1][3], aa.y, b23.y);
            }
        }
        __syncthreads();
    }

    const float* bp = bias + n0 + tx * 8;
    float bb[8];
    *(float4*)(bb)     = *(const float4*)(bp);
    *(float4*)(bb + 4) = *(const float4*)(bp + 4);
#pragma unroll
    for (int i = 0; i < 8; i++) {
        const int m    = m0 + ty * 8 + i;
        const int bidx = m >> 11;       // / T
        const int tdx  = m & (T_SZ - 1);
        float* op = g_xw + ((size_t)tdx * B_SZ + bidx) * G4H + n0 + tx * 8;
        float o[8];
        union { unsigned long long u; float2 f; } cv;
#pragma unroll
        for (int j = 0; j < 4; j++) {
            cv.u = acc2[i][j];
            o[2 * j]     = cv.f.x + bb[2 * j];
            o[2 * j + 1] = cv.f.y + bb[2 * j + 1];
        }
        *(float4*)(op)     = *(const float4*)(o);
        *(float4*)(op + 4) = *(const float4*)(o + 4);
    }
}

// ---------------- Recurrence: persistent, 4 groups x 32 CTAs ----------------
// Group g: batches [8g, 8g+8). CTA r owns 64 z-columns.
// Thread layout: pair p = tid>>3 (0..31) owns local cols {2p, 2p+1};
// kc = tid&7 owns k-range [kc*64, kc*64+64). Weights: 64 u64 regs/thread.
// Each 16B h-load now feeds 4 FFMA2 (was 2), halving LDS issue; the 68-float
// chunk stride makes every LDS.128 one conflict-free broadcast wavefront.

#define HS_CHUNK 68                        // 64 + 4 pad -> kc chunks on distinct banks
#define HS_BB    (8 * HS_CHUNK)            // 544 floats per batch row

__global__ void __launch_bounds__(256) lstm_rec_kernel(
    const float* __restrict__ c0, const float* __restrict__ h0,
    const float* __restrict__ Wh,
    float* __restrict__ outC, float* __restrict__ outH, float* __restrict__ outY)
{
    __shared__ float h_s[8 * HS_BB];   // staged h, 8 batches (17.4 KB)
    __shared__ float z_s[8 * 64];      // hw partials
    __shared__ float c_s[128];         // cell state (8 batches x 16 cols)

    const int tid = threadIdx.x;
    const int grp = blockIdx.x >> 5;
    const int r   = blockIdx.x & 31;
    const int b0  = grp * 8;

    const int p   = tid >> 3;                         // 0..31 column pair
    const int kc  = tid & 7;                          // k chunk (64 k each)
    const int lcA = 2 * p, lcB = 2 * p + 1;
    const int gcolA = ((lcA >> 4) << 9) + (r << 4) + (lcA & 15);
    const int gcolB = ((lcB >> 4) << 9) + (r << 4) + (lcB & 15);

    // ---- Load this thread's Wh slice into registers (packed k-pairs) ----
    unsigned long long w2A[32], w2B[32];
#pragma unroll
    for (int j = 0; j < 32; j++) {
        const size_t k = (size_t)(kc * 64 + 2 * j);
        w2A[j] = pack2(Wh[k * G4H + gcolA], Wh[(k + 1) * G4H + gcolA]);
        w2B[j] = pack2(Wh[k * G4H + gcolB], Wh[(k + 1) * G4H + gcolB]);
    }

    // Init c (block-local) and h buffer 0 (owned slice only)
    if (tid < 128) {
        int bb = tid >> 4, jj = tid & 15;
        int b = b0 + bb, j = (r << 4) + jj;
        c_s[tid] = c0[b * H_SZ + j];
        g_h[b * H_SZ + j] = h0[b * H_SZ + j];
    }
    __syncthreads();
    if (tid < 32)   // publish h(0): consumer=tid's line, producer slot r
        slot_release(&g_flag[(grp * 32 + tid) * 32 + r], 1u);

    for (int t = 0; t < T_SZ; t++) {
        const int buf = t & 1;
        const unsigned target = (unsigned)(t + 1);

        // Prefetch xw (depends only on t) before the wait - overlaps DRAM latency.
        float xw0 = 0.f, xw1 = 0.f, xw2 = 0.f, xw3 = 0.f;
        if (tid < 128) {
            int bb = tid >> 4, jj = tid & 15;
            const float* xp = g_xw + ((size_t)t * B_SZ + b0 + bb) * G4H + (r << 4) + jj;
            xw0 = __ldg(xp);
            xw1 = __ldg(xp + 512);
            xw2 = __ldg(xp + 1024);
            xw3 = __ldg(xp + 1536);
        }

        // ---- wait: all producers published h[buf] (one private 128B line) ----
        if (tid < 32) {
            const unsigned* fl = &g_flag[(grp * 32 + r) * 32];
            unsigned v;
            do { v = slot_acquire(fl + tid); }
            while (!__all_sync(0xFFFFFFFFu, v >= target));
        }
        __syncthreads();   // all warps must see the publish before loading h

        // ---- stage h for the group's 8 batches (padded kc-chunks) ----
        const float* hg = g_h + buf * (B_SZ * H_SZ) + b0 * H_SZ;
#pragma unroll
        for (int it = 0; it < 4; it++) {
            int idx = tid + it * 256;              // 0..1023 float4 slots
            int bbl = idx >> 7, q = idx & 127;
            float4 v = __ldcg((const float4*)(hg + bbl * H_SZ) + q);
            *(float4*)(h_s + bbl * HS_BB + (q >> 4) * HS_CHUNK + (q & 15) * 4) = v;
        }
        __syncthreads();

        // ---- h @ Wh partials: 8 batches, 2 cols/thread vs register Wh ----
#pragma unroll 2
        for (int bbt = 0; bbt < 8; bbt++) {
            const ulonglong2* hp =
                (const ulonglong2*)(h_s + bbt * HS_BB + kc * HS_CHUNK);
            unsigned long long aA0 = 0ull, aA1 = 0ull, aB0 = 0ull, aB1 = 0ull;
#pragma unroll
            for (int i = 0; i < 8; i++) {
                ulonglong2 hv0 = hp[2 * i];
                ulonglong2 hv1 = hp[2 * i + 1];
                ffma2(aA0, w2A[4 * i],     hv0.x);
                ffma2(aA1, w2A[4 * i + 1], hv0.y);
                ffma2(aB0, w2B[4 * i],     hv0.x);
                ffma2(aB1, w2B[4 * i + 1], hv0.y);
                ffma2(aA0, w2A[4 * i + 2], hv1.x);
                ffma2(aA1, w2A[4 * i + 3], hv1.y);
                ffma2(aB0, w2B[4 * i + 2], hv1.x);
                ffma2(aB1, w2B[4 * i + 3], hv1.y);
            }
            float sA = sum2(add2(aA0, aA1));
            float sB = sum2(add2(aB0, aB1));
            // reduce over the 8 kc lanes (lanes p*8 .. p*8+7 of the warp)
            sA += __shfl_xor_sync(0xFFFFFFFFu, sA, 1);
            sB += __shfl_xor_sync(0xFFFFFFFFu, sB, 1);
            sA += __shfl_xor_sync(0xFFFFFFFFu, sA, 2);
            sB += __shfl_xor_sync(0xFFFFFFFFu, sB, 2);
            sA += __shfl_xor_sync(0xFFFFFFFFu, sA, 4);
            sB += __shfl_xor_sync(0xFFFFFFFFu, sB, 4);
            if (kc == 0)
                *(float2*)&z_s[bbt * 64 + lcA] = make_float2(sA, sB);
        }
        __syncthreads();

        // ---- gates + state update (128 threads: 8 batches x 16 cols) ----
        if (tid < 128) {
            int bb = tid >> 4, jj = tid & 15;
            float zi = z_s[bb * 64 + jj]      + xw0;
            float zf = z_s[bb * 64 + 16 + jj] + xw1;
            float zg = z_s[bb * 64 + 32 + jj] + xw2;
            float zo = z_s[bb * 64 + 48 + jj] + xw3;
            float ig = fsig(zi);
            float fg = fsig(zf);
            float gg = ftanh(zg);
            float og = fsig(zo);
            float c  = c_s[tid];
            float cn = fmaf(fg, c, ig * gg);
            c_s[tid] = cn;
            float hn = og * ftanh(cn);
            int b = b0 + bb, j = (r << 4) + jj;
            g_h[(buf ^ 1) * (B_SZ * H_SZ) + b * H_SZ + j] = hn;
            outY[((size_t)b * T_SZ + t) * H_SZ + j] = hn;
            if (t == T_SZ - 1) {
                if (outC) outC[b * H_SZ + j] = cn;
                if (outH) outH[b * H_SZ + j] = hn;
            }
        }
        __syncthreads();   // order all gate-threads' stores before flags

        // ---- publish h[buf^1]: one release per consumer's private line ----
        if (tid < 32)
            slot_release(&g_flag[(grp * 32 + tid) * 32 + r], target + 1u);
    }
}

// ---------------- launch ----------------
extern "C" void kernel_launch(void* const* d_in, const int* in_sizes, int n_in,
                              void* d_out, int out_size)
{
    const float* x    = (const float*)d_in[0];
    const float* c0   = (const float*)d_in[1];
    const float* h0   = (const float*)d_in[2];
    const float* Wi   = (const float*)d_in[3];
    const float* Wh   = (const float*)d_in[4];
    const float* bias = (const float*)d_in[5];

    float* out  = (float*)d_out;
    float* outC = nullptr;
    float* outH = nullptr;
    float* outY = out;
    const long long full = 2LL * B_SZ * H_SZ + (long long)B_SZ * T_SZ * H_SZ;
    if ((long long)out_size == full) {
        outC = out;
        outH = out + B_SZ * H_SZ;
        outY = out + 2 * B_SZ * H_SZ;
    }

    pregemm_kernel<<<dim3(G4H / 128, (B_SZ * T_SZ) / 128), 256>>>(x, Wi, bias);
    lstm_rec_kernel<<<128, 256>>>(c0, h0, Wh, outC, outH, outY);
}